// round 1
// baseline (speedup 1.0000x reference)
#include <cuda_runtime.h>
#include <cuda_bf16.h>

#define SH_C0 0.28209479177387814f
#define SH_C1 0.4886025119029199f

__device__ __constant__ float SH_C2d[5] = {1.0925484305920792f, -1.0925484305920792f, 0.31539156525252005f, -1.0925484305920792f, 0.5462742152960396f};
__device__ __constant__ float SH_C3d[7] = {-0.5900435899266435f, 2.890611442640554f, -0.4570457994644658f, 0.3731763325901154f, -0.4570457994644658f, 1.445305721320277f, -0.5900435899266435f};

__global__ void __launch_bounds__(256)
gsh_kernel(const float* __restrict__ means,
           const float* __restrict__ fdc,
           const float* __restrict__ frest,
           const float* __restrict__ opac,
           const float* __restrict__ c2w,
           const int*   __restrict__ mask,
           const int*   __restrict__ step,
           float* __restrict__ out_rgb,
           float* __restrict__ out_opac,
           int M)
{
    int i = blockIdx.x * blockDim.x + threadIdx.x;
    if (i >= M) return;

    const int idx = __ldg(mask + i);

    const float camx = __ldg(c2w + 3);
    const float camy = __ldg(c2w + 7);
    const float camz = __ldg(c2w + 11);

    const float* mp = means + 3ll * idx;
    float dx = __ldg(mp + 0) - camx;
    float dy = __ldg(mp + 1) - camy;
    float dz = __ldg(mp + 2) - camz;
    float inv = rsqrtf(dx * dx + dy * dy + dz * dz);
    float x = dx * inv, y = dy * inv, z = dz * inv;

    int n = min(__ldg(step) / 1000, 3);

    // SH basis, degree <= 3 (16 coefficients)
    float sh[16];
    sh[0] = SH_C0;
    sh[1] = -SH_C1 * y;
    sh[2] =  SH_C1 * z;
    sh[3] = -SH_C1 * x;
    float xx = x * x, yy = y * y, zz = z * z;
    float xy = x * y, yz = y * z, xz = x * z;
    sh[4] = SH_C2d[0] * xy;
    sh[5] = SH_C2d[1] * yz;
    sh[6] = SH_C2d[2] * (2.0f * zz - xx - yy);
    sh[7] = SH_C2d[3] * xz;
    sh[8] = SH_C2d[4] * (xx - yy);
    sh[9]  = SH_C3d[0] * y * (3.0f * xx - yy);
    sh[10] = SH_C3d[1] * xy * z;
    sh[11] = SH_C3d[2] * y * (4.0f * zz - xx - yy);
    sh[12] = SH_C3d[3] * z * (2.0f * zz - 3.0f * xx - 3.0f * yy);
    sh[13] = SH_C3d[4] * x * (4.0f * zz - xx - yy);
    sh[14] = SH_C3d[5] * z * (xx - yy);
    sh[15] = SH_C3d[6] * x * (xx - 3.0f * yy);

    const int k = (n + 1) * (n + 1);

    // base 0 from features_dc
    const float* f0 = fdc + 3ll * idx;
    float r = sh[0] * __ldg(f0 + 0);
    float g = sh[0] * __ldg(f0 + 1);
    float b = sh[0] * __ldg(f0 + 2);

    // bases 1..15 from features_rest (row = 45 floats)
    const float* fr = frest + 45ll * idx;
#pragma unroll
    for (int j = 1; j < 16; ++j) {
        if (j < k) {
            float c = sh[j];
            r += c * __ldg(fr + (j - 1) * 3 + 0);
            g += c * __ldg(fr + (j - 1) * 3 + 1);
            b += c * __ldg(fr + (j - 1) * 3 + 2);
        }
    }

    r = fmaxf(r + 0.5f, 0.0f);
    g = fmaxf(g + 0.5f, 0.0f);
    b = fmaxf(b + 0.5f, 0.0f);

    out_rgb[3ll * i + 0] = r;
    out_rgb[3ll * i + 1] = g;
    out_rgb[3ll * i + 2] = b;
    out_opac[i] = __ldg(opac + idx);
}

extern "C" void kernel_launch(void* const* d_in, const int* in_sizes, int n_in,
                              void* d_out, int out_size)
{
    const float* means = (const float*)d_in[0];   // N*3
    const float* fdc   = (const float*)d_in[1];   // N*3
    const float* frest = (const float*)d_in[2];   // N*45
    const float* opac  = (const float*)d_in[3];   // N
    const float* c2w   = (const float*)d_in[4];   // 12
    const int*   mask  = (const int*)d_in[5];     // M (int32)
    const int*   step  = (const int*)d_in[6];     // 1

    int M = in_sizes[5];
    float* out_rgb  = (float*)d_out;          // M*3
    float* out_opac = (float*)d_out + 3ll * M; // M

    int threads = 256;
    int blocks = (M + threads - 1) / threads;
    gsh_kernel<<<blocks, threads>>>(means, fdc, frest, opac, c2w, mask, step,
                                    out_rgb, out_opac, M);
}